// round 1
// baseline (speedup 1.0000x reference)
#include <cuda_runtime.h>
#include <cstdint>
#include <cstddef>

#define NB    16
#define CC    192
#define HH    56
#define WW    56
#define HWP   (HH*WW)          // 3136
#define HEADS 6
#define CHN   32
#define KT    486              // 81 * 6
#define SCALE 0.17677669529663689f   // 32^-0.5

// ---------------- scratch (device globals; no runtime allocation) -------------
__device__ float g_v  [NB*CC*HWP];                  // value projection   (38.5 MB)
__device__ float g_att[(size_t)NB*HWP*KT];          // softmaxed attention (97.5 MB)
__device__ float g_fold[NB*CC*HWP];                 // folded result      (38.5 MB)

// ---------------- packed f32x2 helpers ---------------------------------------
#define FMA2(acc,a,b) asm("fma.rn.f32x2 %0, %1, %2, %0;" : "+l"(acc) : "l"(a), "l"(b))

__device__ __forceinline__ unsigned long long pack2(float x, float y) {
    unsigned long long r;
    asm("mov.b64 %0, {%1, %2};" : "=l"(r) : "r"(__float_as_uint(x)), "r"(__float_as_uint(y)));
    return r;
}
__device__ __forceinline__ void unpack2(unsigned long long v, float& x, float& y) {
    unsigned int lo, hi;
    asm("mov.b64 {%0, %1}, %2;" : "=r"(lo), "=r"(hi) : "l"(v));
    x = __uint_as_float(lo); y = __uint_as_float(hi);
}

// ============================================================================
// Kernel A/D: 192x192 pointwise GEMM over pixels.
//   Out[n,d,hw] = sum_c X[n,c,hw] * Wm[c,d] (+ bias[d])
// 192 threads (one per output channel), 64 pixels per tile (32 f32x2 pairs),
// weight matrix resident in smem, grid-stride over tiles to amortize W load.
// Dynamic smem: wsm[192*192] + xsm region [192*66] (x at stride 64, output
// staging at stride 66 -> conflict-free readback).
// ============================================================================
#define GEMM_SMEM_FLOATS (192*192 + 192*66)

__global__ void __launch_bounds__(192, 1) gemm192_kernel(
    const float* __restrict__ X, const float* __restrict__ Wm,
    const float* __restrict__ bias, float* __restrict__ Out, int nTiles)
{
    extern __shared__ float sm[];
    float* wsm = sm;               // 192*192
    float* xsm = sm + 192*192;     // 192*66 region (dual-purpose)
    const int tid = threadIdx.x;

    for (int i = tid; i < 192*192; i += 192) wsm[i] = Wm[i];
    float b = bias ? bias[tid] : 0.0f;
    const unsigned long long b2 = pack2(b, b);

    for (int t = blockIdx.x; t < nTiles; t += gridDim.x) {
        const int n   = t / 49;
        const int hw0 = (t % 49) * 64;
        __syncthreads();                       // wsm ready / xsm free
        for (int i = tid; i < 192*64; i += 192) {
            int c = i >> 6, p = i & 63;
            xsm[i] = X[((size_t)(n*CC + c))*HWP + hw0 + p];
        }
        __syncthreads();

        unsigned long long acc[32];
        #pragma unroll
        for (int i = 0; i < 32; i++) acc[i] = b2;

        #pragma unroll 2
        for (int c = 0; c < 192; c++) {
            float w = wsm[c*192 + tid];
            unsigned long long w2 = pack2(w, w);
            const ulonglong2* xr = (const ulonglong2*)(xsm + c*64);
            #pragma unroll
            for (int k = 0; k < 16; k++) {
                ulonglong2 xv = xr[k];
                FMA2(acc[2*k  ], xv.x, w2);
                FMA2(acc[2*k+1], xv.y, w2);
            }
        }
        __syncthreads();
        // stage output at row stride 66 (8B-aligned pairs, conflict-free read)
        #pragma unroll
        for (int k = 0; k < 32; k++)
            *(unsigned long long*)(xsm + tid*66 + 2*k) = acc[k];
        __syncthreads();
        for (int i = tid; i < 192*64; i += 192) {
            int d = i >> 6, p = i & 63;
            Out[((size_t)(n*CC + d))*HWP + hw0 + p] = xsm[d*66 + p];
        }
    }
}

// ============================================================================
// Kernel B: attention logits GEMM [192 x 486] + fused scaled softmax over kin.
// One block per image row (56 pixels = 28 f32x2 pairs). 512 threads, thread k
// owns attention column k (k<486). Wa streamed from L2 (373KB, L2-resident).
// Dynamic smem: xs[192*56] + logits ls[56*486].
// ============================================================================
#define ATT_SMEM_FLOATS (192*56 + 56*KT)

__global__ void __launch_bounds__(512, 1) att_kernel(
    const float* __restrict__ X, const float* __restrict__ Wa,
    const float* __restrict__ ba, float* __restrict__ Att)
{
    extern __shared__ float sm[];
    float* xs = sm;                // 192*56
    float* ls = sm + 192*56;       // 56*486
    const int tid = threadIdx.x;
    const int t   = blockIdx.x;
    const int n   = t / 56;
    const int hw0 = (t % 56) * 56;

    for (int i = tid; i < 192*56; i += 512) {
        int c = i / 56, p = i - c*56;
        xs[i] = X[((size_t)(n*CC + c))*HWP + hw0 + p];
    }
    __syncthreads();

    const int k = tid;
    if (k < KT) {
        unsigned long long acc[28];
        float b = ba[k];
        unsigned long long b2 = pack2(b, b);
        #pragma unroll
        for (int i = 0; i < 28; i++) acc[i] = b2;

        #pragma unroll 2
        for (int c = 0; c < 192; c++) {
            float w = Wa[c*KT + k];
            unsigned long long w2 = pack2(w, w);
            const ulonglong2* xr = (const ulonglong2*)(xs + c*56);
            #pragma unroll
            for (int q = 0; q < 14; q++) {
                ulonglong2 xv = xr[q];
                FMA2(acc[2*q  ], xv.x, w2);
                FMA2(acc[2*q+1], xv.y, w2);
            }
        }
        #pragma unroll
        for (int i = 0; i < 28; i++) {
            float a0, a1; unpack2(acc[i], a0, a1);
            ls[(2*i  )*KT + k] = a0;
            ls[(2*i+1)*KT + k] = a1;
        }
    }
    __syncthreads();

    // softmax over kin (groups of 9): 56 pixels * 54 (head,kout) groups
    for (int g = tid; g < 56*54; g += 512) {
        int p = g / 54, r = g - p*54;
        const float* src = ls + p*KT + r*9;
        float m = src[0];
        #pragma unroll
        for (int i = 1; i < 9; i++) m = fmaxf(m, src[i]);
        float e[9], s = 0.0f;
        #pragma unroll
        for (int i = 0; i < 9; i++) { e[i] = __expf((src[i]-m)*SCALE); s += e[i]; }
        float inv = 1.0f / s;
        float* dst = Att + ((size_t)(n*HWP + hw0 + p))*KT + r*9;
        #pragma unroll
        for (int i = 0; i < 9; i++) dst[i] = e[i]*inv;
    }
}

// ============================================================================
// Kernel C: aggregation + fold (gather formulation, race-free).
//  folded[n,c,y,x] = sum_{(i,j)} sum_{(a,b)} att[n,head,(y+1-i,x+1-j),(i,j),(a,b)]
//                                * v[n,c, y+(a-i), x+(b-j)]      (zero outside)
// Block: 8x8 pixel tile, v window 12x12 (halo 2, zero-padded) for all 192
// channels in smem [192][145] (odd stride -> conflict-free). 192 threads; a
// thread owns (head, q) so the 81 att weights load ONCE and are reused over
// 32 channels (FMA-bound, not LDG-bound). OOB source pixels -> zero weights.
// Dynamic smem: vsm[192*145] + fsm[192*64].
// ============================================================================
#define AGG_SMEM_FLOATS (192*145 + 192*64)

__global__ void __launch_bounds__(192, 1) agg_kernel(
    const float* __restrict__ V, const float* __restrict__ Att,
    float* __restrict__ Fold)
{
    extern __shared__ float sm[];
    float* vsm = sm;               // 192*145 (pos = ly*12+lx, 144 used)
    float* fsm = sm + 192*145;     // 192*64
    const int tid = threadIdx.x;
    const int blk = blockIdx.x;
    const int n  = blk / 49;
    const int tt = blk - n*49;
    const int y0 = (tt / 7) * 8, x0 = (tt % 7) * 8;

    // load v window [y0-2, y0+10) x [x0-2, x0+10), zero-fill OOB
    for (int i = tid; i < 192*144; i += 192) {
        int c = i / 144, pos = i - c*144;
        int ly = pos / 12, lx = pos - ly*12;
        int gy = y0 - 2 + ly, gx = x0 - 2 + lx;
        float val = 0.0f;
        if (gy >= 0 && gy < HH && gx >= 0 && gx < WW)
            val = V[((size_t)(n*CC + c))*HWP + gy*WW + gx];
        vsm[c*145 + pos] = val;
    }
    __syncthreads();

    #pragma unroll 1
    for (int s = 0; s < 2; s++) {
        const int task = tid + s*192;       // 384 tasks = 6 heads * 64 pixels
        const int head = task >> 6;
        const int q    = task & 63;
        const int qy = q >> 3, qx = q & 7;
        const int gy = y0 + qy, gx = x0 + qx;

        // gather 81 attention weights (9 source pixels x 9 kin); OOB -> 0
        float w[81];
        #pragma unroll
        for (int i = 0; i < 3; i++)
        #pragma unroll
        for (int j = 0; j < 3; j++) {
            int py = gy + 1 - i, px = gx + 1 - j;
            if (py >= 0 && py < HH && px >= 0 && px < WW) {
                const float* ab = Att + ((size_t)n*HWP + py*WW + px)*KT
                                      + head*81 + (i*3+j)*9;
                #pragma unroll
                for (int u = 0; u < 9; u++) w[(i*3+j)*9+u] = ab[u];
            } else {
                #pragma unroll
                for (int u = 0; u < 9; u++) w[(i*3+j)*9+u] = 0.0f;
            }
        }

        #pragma unroll 1
        for (int ch = 0; ch < CHN; ch++) {
            const int cg = head*CHN + ch;
            const float* vb = vsm + cg*145;
            float vv[25];                        // 5x5 window around q
            #pragma unroll
            for (int dy = 0; dy < 5; dy++)
            #pragma unroll
            for (int dx = 0; dx < 5; dx++)
                vv[dy*5+dx] = vb[(qy+dy)*12 + (qx+dx)];

            float partial[4] = {0.f, 0.f, 0.f, 0.f};
            #pragma unroll
            for (int i = 0; i < 3; i++)
            #pragma unroll
            for (int j = 0; j < 3; j++)
            #pragma unroll
            for (int a = 0; a < 3; a++)
            #pragma unroll
            for (int bb = 0; bb < 3; bb++) {
                const int widx = (i*3+j)*9 + a*3 + bb;
                partial[widx & 3] += w[widx] * vv[(a-i+2)*5 + (bb-j+2)];
            }
            fsm[cg*64 + q] = (partial[0]+partial[1]) + (partial[2]+partial[3]);
        }
    }
    __syncthreads();

    for (int i = tid; i < 192*64; i += 192) {
        int c = i >> 6, q = i & 63;
        int qy = q >> 3, qx = q & 7;
        Fold[((size_t)(n*CC + c))*HWP + (y0+qy)*WW + (x0+qx)] = fsm[i];
    }
}

// ============================================================================
// Launch
// ============================================================================
extern "C" void kernel_launch(void* const* d_in, const int* in_sizes, int n_in,
                              void* d_out, int out_size)
{
    const float* x  = (const float*)d_in[0];
    const float* Wv = (const float*)d_in[1];
    const float* Wa = (const float*)d_in[2];
    const float* ba = (const float*)d_in[3];
    const float* Wp = (const float*)d_in[4];
    const float* bp = (const float*)d_in[5];
    float* out = (float*)d_out;

    float *vp, *ap, *fp;
    cudaGetSymbolAddress((void**)&vp, g_v);
    cudaGetSymbolAddress((void**)&ap, g_att);
    cudaGetSymbolAddress((void**)&fp, g_fold);

    const int smemGemm = GEMM_SMEM_FLOATS * 4;   // 198,144 B
    const int smemAtt  = ATT_SMEM_FLOATS  * 4;   // 151,872 B
    const int smemAgg  = AGG_SMEM_FLOATS  * 4;   // 160,512 B
    cudaFuncSetAttribute(gemm192_kernel, cudaFuncAttributeMaxDynamicSharedMemorySize, smemGemm);
    cudaFuncSetAttribute(att_kernel,     cudaFuncAttributeMaxDynamicSharedMemorySize, smemAtt);
    cudaFuncSetAttribute(agg_kernel,     cudaFuncAttributeMaxDynamicSharedMemorySize, smemAgg);

    const int nTiles = NB * 49;                   // 784 tiles of 64 pixels

    // value projection: v = x @ Wv
    gemm192_kernel<<<148, 192, smemGemm>>>(x, Wv, nullptr, vp, nTiles);
    // attention logits + softmax
    att_kernel<<<NB*56, 512, smemAtt>>>(x, Wa, ba, ap);
    // aggregation + fold
    agg_kernel<<<NB*49, 192, smemAgg>>>(vp, ap, fp);
    // output projection: out = folded @ Wp + bp
    gemm192_kernel<<<148, 192, smemGemm>>>(fp, Wp, bp, out, nTiles);
}